// round 13
// baseline (speedup 1.0000x reference)
#include <cuda_runtime.h>
#include <cstdint>
typedef unsigned long long ULL;

#define Tn   4096
#define INn  32
#define Hn   512
#define OUTn 32
#define TPB  256
#define CLC  16
#define NCTA 112

// dynamic smem: weights = 8 warps x 5 slots x 16 j x 256B = 160KB, then h double buffer
#define OFF_HBUF 163840
#define SMEM_SZ  167936

__device__ float g_X[3][(size_t)Tn * 2048];     // gate-major x-parts (incl. bias)
__device__ float g_h[3][(size_t)Tn * Hn];
__device__ __align__(128) unsigned g_hflag[3][16][32];      // [layer][crank][warp]
__device__ __align__(128) unsigned g_xflag[2][2][16][32];   // [which X][parity][crank]
__device__ __align__(128) ULL g_cnt[16];
__device__ __align__(128) ULL g_gen[16];

__device__ __forceinline__ unsigned ld_acq(const unsigned* p) {
    unsigned v; asm volatile("ld.global.acquire.gpu.u32 %0, [%1];" : "=r"(v) : "l"(p) : "memory"); return v;
}
__device__ __forceinline__ void st_rel(unsigned* p, unsigned v) {
    asm volatile("st.global.release.gpu.u32 [%0], %1;" :: "l"(p), "r"(v) : "memory");
}
__device__ __forceinline__ void ffma2(ULL& d, ULL a, ULL b) {
    asm("fma.rn.f32x2 %0, %1, %2, %0;" : "+l"(d) : "l"(a), "l"(b));
}
__device__ __forceinline__ float f2lo(ULL v) { return __uint_as_float((unsigned)v); }
__device__ __forceinline__ float f2hi(ULL v) { return __uint_as_float((unsigned)(v >> 32)); }
__device__ __forceinline__ uint32_t smem_u32(const void* p) {
    uint32_t a; asm("{ .reg .u64 t; cvta.to.shared.u64 t, %1; cvt.u32.u64 %0, t; }" : "=r"(a) : "l"(p)); return a;
}
__device__ __forceinline__ uint32_t mapa_rank(uint32_t la, uint32_t r) {
    uint32_t o; asm("mapa.shared::cluster.u32 %0, %1, %2;" : "=r"(o) : "r"(la), "r"(r)); return o;
}
__device__ __forceinline__ void st_cluster_u64(uint32_t a, ULL v) {
    asm volatile("st.shared::cluster.u64 [%0], %1;" :: "r"(a), "l"(v) : "memory");
}
__device__ __forceinline__ void mbar_init(uint32_t a, unsigned c) {
    asm volatile("mbarrier.init.shared.b64 [%0], %1;" :: "r"(a), "r"(c) : "memory");
}
__device__ __forceinline__ void mbar_arrive_cl(uint32_t a) {
    asm volatile("mbarrier.arrive.release.cluster.shared::cluster.b64 _, [%0];" :: "r"(a) : "memory");
}
__device__ __forceinline__ void mbar_wait(uint32_t a, unsigned par) {
    unsigned done;
    do {
        asm volatile("{\n\t.reg .pred p;\n\t"
            "mbarrier.try_wait.parity.acquire.cluster.shared::cta.b64 p, [%1], %2, 0x989680;\n\t"
            "selp.b32 %0, 1, 0, p;\n\t}"
            : "=r"(done) : "r"(a), "r"(par) : "memory");
    } while (!done);
}
__device__ __forceinline__ float fast_sig(float x) {
    x = fmaxf(x, -80.0f); return __fdividef(1.0f, 1.0f + __expf(-x));
}
__device__ __forceinline__ float fast_tanh(float x) {
    x = fminf(15.0f, fmaxf(-15.0f, x));
    float e = __expf(2.0f * x); return __fdividef(e - 1.0f, e + 1.0f);
}
#define RED16(v) { v+=__shfl_xor_sync(0xffffffffu,v,1); v+=__shfl_xor_sync(0xffffffffu,v,2); \
                   v+=__shfl_xor_sync(0xffffffffu,v,4); v+=__shfl_xor_sync(0xffffffffu,v,8); }
#define RED32(v) { v+=__shfl_xor_sync(0xffffffffu,v,16); RED16(v) }

// local row L (0..127) -> global gate row: gate = L&3, unit = crank*32 + (L>>2)
#define ROWR(L) ((size_t)(((L) & 3) * Hn + crank * 32 + ((L) >> 2)))

__global__ void __launch_bounds__(TPB, 1) lstm_warp_kernel(
    const float* __restrict__ seq,
    const float* __restrict__ Wih1, const float* __restrict__ Whh1,
    const float* __restrict__ bih1, const float* __restrict__ bhh1,
    const float* __restrict__ Wih2, const float* __restrict__ Whh2,
    const float* __restrict__ bih2, const float* __restrict__ bhh2,
    const float* __restrict__ Wih3, const float* __restrict__ Whh3,
    const float* __restrict__ bih3, const float* __restrict__ bhh3,
    const float* __restrict__ Wout, const float* __restrict__ bout,
    float* __restrict__ out)
{
    extern __shared__ char dsm[];
    ULL*   wsm   = (ULL*)dsm;                    // 160 KB weights
    ULL*   hbull = (ULL*)(dsm + OFF_HBUF);       // 2 x 256 ULL, swizzled
    float* hbuf  = (float*)(dsm + OFF_HBUF);
    float* sseq  = (float*)dsm;                  // phase-0 alias

    __shared__ ULL mbar[2];
    __shared__ unsigned sbh[3], sbx[4];
    __shared__ ULL sg;

    const int tid = threadIdx.x, w = tid >> 5, lane = tid & 31;
    const int hf = lane >> 4, l16 = lane & 15;
    const int cta = blockIdx.x, clu = cta >> 4, crank = cta & 15;

    if (tid < 3) sbh[tid] = *(volatile unsigned*)&g_hflag[tid][0][0];
    if (tid >= 3 && tid < 7) sbx[tid-3] = *(volatile unsigned*)&g_xflag[(tid-3)>>1][(tid-3)&1][0][0];
    if (tid == 7) sg = *(volatile ULL*)&g_gen[0];
    __syncthreads();

    // ================= Phase 0: X1 = seq @ Wih1^T + b =================
    {
        float wx[3], bb[3];
        #pragma unroll
        for (int p = 0; p < 3; p++) {
            int row = cta * 8 + w + p * 896;
            bool v = row < 2048; int R = v ? row : 0;
            wx[p] = v ? Wih1[R * INn + lane] : 0.0f;
            bb[p] = v ? (bih1[R] + bhh1[R]) : 0.0f;
        }
        for (int t0 = 0; t0 < Tn; t0 += 32) {
            __syncthreads();
            {
                const float4 v = *(const float4*)(seq + (size_t)t0 * INn + tid * 4);
                int tl = (tid * 4) >> 5, k = (tid * 4) & 31;
                float* pp = &sseq[tl * 33 + k];
                pp[0] = v.x; pp[1] = v.y; pp[2] = v.z; pp[3] = v.w;
            }
            __syncthreads();
            #pragma unroll
            for (int p = 0; p < 3; p++) {
                int row = cta * 8 + w + p * 896;
                if (row < 2048) {
                    float acc = 0.0f;
                    #pragma unroll
                    for (int k = 0; k < INn; k++)
                        acc = fmaf(__shfl_sync(0xffffffffu, wx[p], k), sseq[lane * 33 + k], acc);
                    g_X[0][(size_t)(t0 + lane) * 2048 + row] = acc + bb[p];
                }
            }
        }
    }
    __syncthreads();

    // ================= role assignment + weight fill =================
    const bool rec = (clu < 3);
    int xi = 0, par = 0, up = 0;
    const float* W; const float* fbi = bih2; const float* fbh = bhh2;
    if (rec) {
        W = (clu == 0) ? Whh1 : (clu == 1) ? Whh2 : Whh3;
    } else {
        int f = clu - 3; xi = f >> 1; par = f & 1; up = xi;
        W = (xi == 0) ? Wih2 : Wih3;
        fbi = (xi == 0) ? bih2 : bih3; fbh = (xi == 0) ? bhh2 : bhh3;
    }

    // 3 rows in regs (48 ULL), 5 rows in smem, per half-warp; warp owns 16 rows = 4 units x 4 gates
    ULL wreg[48];
    float fb[8];
    #pragma unroll
    for (int i = 0; i < 3; i++) {
        size_t R = ROWR(w * 16 + hf * 8 + i);
        #pragma unroll
        for (int j = 0; j < 16; j++)
            wreg[i * 16 + j] = *(const ULL*)(W + R * Hn + l16 * 32 + j * 2);
    }
    #pragma unroll
    for (int s = 0; s < 5; s++) {
        size_t R = ROWR(w * 16 + hf * 8 + 3 + s);
        #pragma unroll
        for (int j = 0; j < 16; j++)
            wsm[(((w * 5 + s) * 16 + j) << 5) + lane] = *(const ULL*)(W + R * Hn + l16 * 32 + j * 2);
    }
    #pragma unroll
    for (int i = 0; i < 8; i++) {
        size_t R = ROWR(w * 16 + hf * 8 + i);
        fb[i] = rec ? 0.0f : (fbi[R] + fbh[R]);
    }

    *(float4*)&hbuf[tid * 4] = make_float4(0.f, 0.f, 0.f, 0.f);
    if (rec && tid == 0) { mbar_init(smem_u32(&mbar[0]), 128); mbar_init(smem_u32(&mbar[1]), 128); }
    __syncthreads();
    if (rec) {
        asm volatile("barrier.cluster.arrive.aligned;" ::: "memory");
        asm volatile("barrier.cluster.wait.aligned;" ::: "memory");
    }

    // one-time global barrier
    if (tid == 0) {
        __threadfence();
        ULL old = atomicAdd(&g_cnt[0], 1ULL);
        if (old == (ULL)(NCTA - 1)) {
            g_cnt[0] = 0ULL; __threadfence(); atomicAdd(&g_gen[0], 1ULL);
        }
        volatile ULL* p = &g_gen[0];
        while (*p < sg + 1) { }
        __threadfence();
    }
    __syncthreads();

    if (rec) {
        // ================= recurrent cluster, layer = clu; NO __syncthreads in loop ======
        const unsigned hb = sbh[clu];
        unsigned* myfw = &g_hflag[clu][crank][w];
        float* hout = g_h[clu];
        const float* Xs = g_X[clu];
        const unsigned* xf0 = (clu > 0) ? &g_xflag[clu-1][0][crank][0] : (const unsigned*)0;
        const unsigned* xf1 = (clu > 0) ? &g_xflag[clu-1][1][crank][0] : (const unsigned*)0;
        const unsigned xb0 = (clu > 0) ? sbx[(clu-1)*2+0] : 0u;
        const unsigned xb1 = (clu > 0) ? sbx[(clu-1)*2+1] : 0u;

        const uint32_t mb0 = smem_u32(&mbar[0]);
        // this lane delivers pair (units w*4+2*hf_p, +1) of half hf_p = lane>>4 to rank lane&15
        const uint32_t rdst = mapa_rank(
            smem_u32(&hbull[(((unsigned)(w * 2 + hf)) << 4) | (unsigned)crank]),
            (uint32_t)(lane & 15));
        const uint32_t rbar = mapa_rank(mb0, (uint32_t)(lane & 15));
        float cA = 0.0f, cB = 0.0f;

        for (int t = 0; t < Tn; t++) {
            // ---- x prefetch (per warp; feeder-flag gated for layers 2/3) ----
            if (clu > 0 && lane == 0) {
                const unsigned* fp = (t & 1) ? xf1 : xf0;
                unsigned tgt = ((t & 1) ? xb1 : xb0) + (unsigned)((t >> 1) + 1);
                while ((int)(ld_acq(fp) - tgt) < 0) { }
            }
            __syncwarp();
            ULL xq0 = 0, xq1 = 0, xq2 = 0, xq3 = 0;
            if (l16 == 0) {
                const ULL* xp = (const ULL*)(Xs + (size_t)t * 2048 + crank * 32 + w * 4 + 2 * hf);
                xq0 = xp[0]; xq1 = xp[256]; xq2 = xp[512]; xq3 = xp[768];
            }
            // ---- wait for h(t-1) (per warp) ----
            if (t > 0) {
                if (lane == 0) mbar_wait(mb0 + ((t - 1) & 1) * 8, (unsigned)(((t - 1) >> 1) & 1));
                __syncwarp();
            }

            // ---- GEMV: 8 rows per half-warp ----
            const ULL* hsrc = hbull + ((t + 1) & 1) * 256;
            ULL a0=0,a1=0,a2=0,a3=0,a4=0,a5=0,a6=0,a7=0;
            #pragma unroll
            for (int j = 0; j < 16; j++) {
                ULL hv = hsrc[j * 16 + l16];
                ffma2(a0, wreg[j], hv);       ffma2(a1, wreg[16+j], hv);
                ffma2(a2, wreg[32+j], hv);
                ffma2(a3, wsm[(((w*5+0)*16+j)<<5)+lane], hv);
                ffma2(a4, wsm[(((w*5+1)*16+j)<<5)+lane], hv);
                ffma2(a5, wsm[(((w*5+2)*16+j)<<5)+lane], hv);
                ffma2(a6, wsm[(((w*5+3)*16+j)<<5)+lane], hv);
                ffma2(a7, wsm[(((w*5+4)*16+j)<<5)+lane], hv);
            }
            float r0=f2lo(a0)+f2hi(a0), r1=f2lo(a1)+f2hi(a1), r2=f2lo(a2)+f2hi(a2), r3=f2lo(a3)+f2hi(a3);
            float r4=f2lo(a4)+f2hi(a4), r5=f2lo(a5)+f2hi(a5), r6=f2lo(a6)+f2hi(a6), r7=f2lo(a7)+f2hi(a7);
            RED16(r0) RED16(r1) RED16(r2) RED16(r3) RED16(r4) RED16(r5) RED16(r6) RED16(r7)

            // ---- in-lane LSTM cell epilogue: lanes 0 and 16 own 2 units each ----
            float hA = 0.0f, hB = 0.0f;
            if (l16 == 0) {
                float iA = fast_sig (r0 + f2lo(xq0));
                float fA = fast_sig (r1 + f2lo(xq1));
                float gA = fast_tanh(r2 + f2lo(xq2));
                float oA = fast_sig (r3 + f2lo(xq3));
                cA = fmaf(fA, cA, iA * gA);
                hA = oA * fast_tanh(cA);
                float iB = fast_sig (r4 + f2hi(xq0));
                float fB = fast_sig (r5 + f2hi(xq1));
                float gB = fast_tanh(r6 + f2hi(xq2));
                float oB = fast_sig (r7 + f2hi(xq3));
                cB = fmaf(fB, cB, iB * gB);
                hB = oB * fast_tanh(cB);
            }
            // ---- distribute this warp's 4 h values to all 16 ranks ----
            unsigned plo = __shfl_sync(0xffffffffu, __float_as_uint(hA), lane & 16);
            unsigned phi = __shfl_sync(0xffffffffu, __float_as_uint(hB), lane & 16);
            ULL hv = ((ULL)phi << 32) | plo;
            st_cluster_u64(rdst + (unsigned)(t & 1) * 2048u, hv);
            __syncwarp();
            asm volatile("fence.acq_rel.cluster;" ::: "memory");
            if (lane < 16) mbar_arrive_cl(rbar + (unsigned)(t & 1) * 8u);

            // ---- g_h write + per-warp flag ----
            unsigned q0 = __shfl_sync(0xffffffffu, __float_as_uint(hA), 16);
            unsigned q1 = __shfl_sync(0xffffffffu, __float_as_uint(hB), 16);
            if (lane == 0) {
                float4 h4 = make_float4(hA, hB, __uint_as_float(q0), __uint_as_float(q1));
                *(float4*)(hout + (size_t)t * Hn + crank * 32 + w * 4) = h4;
                st_rel(myfw, hb + (unsigned)(t + 1));
            }
        }
        asm volatile("barrier.cluster.arrive.aligned;" ::: "memory");
        asm volatile("barrier.cluster.wait.aligned;" ::: "memory");
    } else {
        // ================= feeder: X[xi+1][t] = W . g_h[up][t] + b, parity par =================
        const unsigned ub = sbh[up];
        const unsigned xb = sbx[xi * 2 + par];
        unsigned* myf = &g_xflag[xi][par][crank][0];
        float* Xd = g_X[xi + 1];
        const float* hg = g_h[up];

        for (int t = par; t < Tn; t += 2) {
            if (tid < 128) {     // poll all 128 per-warp producer flags
                unsigned tgt = ub + (unsigned)(t + 1);
                const unsigned* fp = &g_hflag[up][tid >> 3][tid & 7];
                while ((int)(ld_acq(fp) - tgt) < 0) { }
            }
            __syncthreads();
            if (tid < 128) {     // coalesced load, swizzled store
                float4 v = *(const float4*)(hg + (size_t)t * Hn + tid * 4);
                int k0 = 2 * tid, k1 = 2 * tid + 1;
                ULL u0 = ((ULL)__float_as_uint(v.y) << 32) | __float_as_uint(v.x);
                ULL u1 = ((ULL)__float_as_uint(v.w) << 32) | __float_as_uint(v.z);
                hbull[((k0 & 15) << 4) | (k0 >> 4)] = u0;
                hbull[((k1 & 15) << 4) | (k1 >> 4)] = u1;
            }
            __syncthreads();

            const ULL* hsrc = hbull;
            ULL a0=0,a1=0,a2=0,a3=0,a4=0,a5=0,a6=0,a7=0;
            #pragma unroll
            for (int j = 0; j < 16; j++) {
                ULL hv = hsrc[j * 16 + l16];
                ffma2(a0, wreg[j], hv);       ffma2(a1, wreg[16+j], hv);
                ffma2(a2, wreg[32+j], hv);
                ffma2(a3, wsm[(((w*5+0)*16+j)<<5)+lane], hv);
                ffma2(a4, wsm[(((w*5+1)*16+j)<<5)+lane], hv);
                ffma2(a5, wsm[(((w*5+2)*16+j)<<5)+lane], hv);
                ffma2(a6, wsm[(((w*5+3)*16+j)<<5)+lane], hv);
                ffma2(a7, wsm[(((w*5+4)*16+j)<<5)+lane], hv);
            }
            float rr[8];
            rr[0]=f2lo(a0)+f2hi(a0); rr[1]=f2lo(a1)+f2hi(a1); rr[2]=f2lo(a2)+f2hi(a2); rr[3]=f2lo(a3)+f2hi(a3);
            rr[4]=f2lo(a4)+f2hi(a4); rr[5]=f2lo(a5)+f2hi(a5); rr[6]=f2lo(a6)+f2hi(a6); rr[7]=f2lo(a7)+f2hi(a7);
            #pragma unroll
            for (int i = 0; i < 8; i++) { RED16(rr[i]) }
            if (l16 == 0) {
                #pragma unroll
                for (int g = 0; g < 4; g++) {
                    float vlo = rr[g] + fb[g];
                    float vhi = rr[4 + g] + fb[4 + g];
                    ULL pv = ((ULL)__float_as_uint(vhi) << 32) | __float_as_uint(vlo);
                    *(ULL*)(Xd + (size_t)t * 2048 + g * 512 + crank * 32 + w * 4 + 2 * hf) = pv;
                }
            }
            __syncthreads();
            if (tid == 0) st_rel(myf, xb + (unsigned)((t >> 1) + 1));
        }
    }

    // ================= final projection (all CTAs) =================
    if (tid < 128) {
        unsigned tgt = sbh[2] + (unsigned)Tn;
        const unsigned* fp = &g_hflag[2][tid >> 3][tid & 7];
        while ((int)(ld_acq(fp) - tgt) < 0) { }
    }
    __syncthreads();

    ULL wo[32];
    float bo4[4];
    #pragma unroll
    for (int oi = 0; oi < 4; oi++) {
        int o = w * 4 + oi;
        #pragma unroll
        for (int j = 0; j < 8; j++)
            wo[oi * 8 + j] = *(const ULL*)(Wout + (size_t)o * Hn + j * 64 + lane * 2);
        bo4[oi] = bout[o];
    }
    const float* h3 = g_h[2];
    for (int t = cta; t < Tn; t += NCTA) {
        __syncthreads();
        if (tid < 128)
            *(float4*)&hbuf[tid * 4] = *(const float4*)(h3 + (size_t)t * Hn + tid * 4);
        __syncthreads();
        const ULL* hh = (const ULL*)hbuf;
        #pragma unroll
        for (int oi = 0; oi < 4; oi++) {
            ULL acc = 0;
            #pragma unroll
            for (int j = 0; j < 8; j++) ffma2(acc, wo[oi * 8 + j], hh[j * 32 + lane]);
            float r = f2lo(acc) + f2hi(acc);
            RED32(r)
            if (lane == 0) out[(size_t)t * OUTn + w * 4 + oi] = r + bo4[oi];
        }
    }
}

extern "C" void kernel_launch(void* const* d_in, const int* in_sizes, int n_in,
                              void* d_out, int out_size) {
    const float* seq  = (const float*)d_in[0];
    const float* Wih1 = (const float*)d_in[1];
    const float* Whh1 = (const float*)d_in[2];
    const float* bih1 = (const float*)d_in[3];
    const float* bhh1 = (const float*)d_in[4];
    const float* Wih2 = (const float*)d_in[5];
    const float* Whh2 = (const float*)d_in[6];
    const float* bih2 = (const float*)d_in[7];
    const float* bhh2 = (const float*)d_in[8];
    const float* Wih3 = (const float*)d_in[9];
    const float* Whh3 = (const float*)d_in[10];
    const float* bih3 = (const float*)d_in[11];
    const float* bhh3 = (const float*)d_in[12];
    const float* Wout = (const float*)d_in[13];
    const float* bout = (const float*)d_in[14];
    float* out = (float*)d_out;

    cudaFuncSetAttribute(lstm_warp_kernel, cudaFuncAttributeMaxDynamicSharedMemorySize, SMEM_SZ);
    cudaFuncSetAttribute(lstm_warp_kernel, cudaFuncAttributeNonPortableClusterSizeAllowed, 1);

    cudaLaunchConfig_t cfg = {};
    cfg.gridDim = {NCTA, 1, 1};
    cfg.blockDim = {TPB, 1, 1};
    cfg.dynamicSmemBytes = SMEM_SZ;
    cudaLaunchAttribute at[1];
    at[0].id = cudaLaunchAttributeClusterDimension;
    at[0].val.clusterDim = {CLC, 1, 1};
    cfg.attrs = at;
    cfg.numAttrs = 1;

    cudaLaunchKernelEx(&cfg, lstm_warp_kernel, seq,
        Wih1, Whh1, bih1, bhh1,
        Wih2, Whh2, bih2, bhh2,
        Wih3, Whh3, bih3, bhh3,
        Wout, bout, out);
}

// round 14
// speedup vs baseline: 3.5136x; 3.5136x over previous
#include <cuda_runtime.h>
#include <cstdint>
typedef unsigned long long ULL;

#define Tn   4096
#define INn  32
#define Hn   512
#define OUTn 32
#define TPB  256
#define CLC  16
#define NCTA 112

// smem layout: weights 128KB, hbuf 2x512f, xring 4x128f, sp 128f
#define OFF_HBUF 131072
#define OFF_XR   135168
#define OFF_SP   137216
#define SMEM_SZ  137728

__device__ float g_X[3][(size_t)Tn * 2048];     // gate-major x-parts (incl. bias)
__device__ float g_h[3][(size_t)Tn * Hn];
__device__ __align__(128) unsigned g_hflag[3][16][32];
__device__ __align__(128) unsigned g_xflag[2][2][16][32];   // [which X][parity][crank]
__device__ __align__(128) ULL g_cnt[16];
__device__ __align__(128) ULL g_gen[16];

__device__ __forceinline__ unsigned ld_acq(const unsigned* p) {
    unsigned v; asm volatile("ld.global.acquire.gpu.u32 %0, [%1];" : "=r"(v) : "l"(p) : "memory"); return v;
}
__device__ __forceinline__ void st_rel(unsigned* p, unsigned v) {
    asm volatile("st.global.release.gpu.u32 [%0], %1;" :: "l"(p), "r"(v) : "memory");
}
__device__ __forceinline__ void ffma2(ULL& d, ULL a, ULL b) {
    asm("fma.rn.f32x2 %0, %1, %2, %0;" : "+l"(d) : "l"(a), "l"(b));
}
__device__ __forceinline__ float f2lo(ULL v) { return __uint_as_float((unsigned)v); }
__device__ __forceinline__ float f2hi(ULL v) { return __uint_as_float((unsigned)(v >> 32)); }
__device__ __forceinline__ uint32_t smem_u32(const void* p) {
    uint32_t a; asm("{ .reg .u64 t; cvta.to.shared.u64 t, %1; cvt.u32.u64 %0, t; }" : "=r"(a) : "l"(p)); return a;
}
__device__ __forceinline__ uint32_t mapa_rank(uint32_t la, uint32_t r) {
    uint32_t o; asm("mapa.shared::cluster.u32 %0, %1, %2;" : "=r"(o) : "r"(la), "r"(r)); return o;
}
__device__ __forceinline__ void st_cluster_u64(uint32_t a, ULL v) {
    asm volatile("st.shared::cluster.u64 [%0], %1;" :: "r"(a), "l"(v) : "memory");
}
__device__ __forceinline__ void mbar_init(uint32_t a, unsigned c) {
    asm volatile("mbarrier.init.shared.b64 [%0], %1;" :: "r"(a), "r"(c) : "memory");
}
__device__ __forceinline__ void mbar_arrive_cl(uint32_t a) {
    asm volatile("mbarrier.arrive.release.cluster.shared::cluster.b64 _, [%0];" :: "r"(a) : "memory");
}
__device__ __forceinline__ void mbar_wait(uint32_t a, unsigned par) {
    unsigned done;
    do {
        asm volatile("{\n\t.reg .pred p;\n\t"
            "mbarrier.try_wait.parity.acquire.cluster.shared::cta.b64 p, [%1], %2, 0x989680;\n\t"
            "selp.b32 %0, 1, 0, p;\n\t}"
            : "=r"(done) : "r"(a), "r"(par) : "memory");
    } while (!done);
}
__device__ __forceinline__ float fast_sig(float x) {
    x = fmaxf(x, -80.0f); return __fdividef(1.0f, 1.0f + __expf(-x));
}
__device__ __forceinline__ float fast_tanh(float x) {
    x = fminf(15.0f, fmaxf(-15.0f, x));
    float e = __expf(2.0f * x); return __fdividef(e - 1.0f, e + 1.0f);
}
#define RED16(v) { v+=__shfl_xor_sync(0xffffffffu,v,1); v+=__shfl_xor_sync(0xffffffffu,v,2); \
                   v+=__shfl_xor_sync(0xffffffffu,v,4); v+=__shfl_xor_sync(0xffffffffu,v,8); }
#define RED32(v) { v+=__shfl_xor_sync(0xffffffffu,v,16); RED16(v) }

__global__ void __launch_bounds__(TPB, 1) lstm_pipe2_kernel(
    const float* __restrict__ seq,
    const float* __restrict__ Wih1, const float* __restrict__ Whh1,
    const float* __restrict__ bih1, const float* __restrict__ bhh1,
    const float* __restrict__ Wih2, const float* __restrict__ Whh2,
    const float* __restrict__ bih2, const float* __restrict__ bhh2,
    const float* __restrict__ Wih3, const float* __restrict__ Whh3,
    const float* __restrict__ bih3, const float* __restrict__ bhh3,
    const float* __restrict__ Wout, const float* __restrict__ bout,
    float* __restrict__ out)
{
    extern __shared__ char dsm[];
    ULL*   wsm   = (ULL*)dsm;                    // 128 KB weights
    ULL*   hbull = (ULL*)(dsm + OFF_HBUF);       // 2 x 256 ULL, swizzled
    float* hbuf  = (float*)(dsm + OFF_HBUF);
    float* xring = (float*)(dsm + OFF_XR);       // 4 x 128
    float* sp    = (float*)(dsm + OFF_SP);       // 128
    float* sseq  = (float*)dsm;                  // phase-0 alias

    __shared__ ULL mbar[2];
    __shared__ unsigned sbh[3], sbx[4];
    __shared__ ULL sg;

    const int tid = threadIdx.x, w = tid >> 5, lane = tid & 31;
    const int hf = lane >> 4, l16 = lane & 15;
    const int cta = blockIdx.x, clu = cta >> 4, crank = cta & 15;

    if (tid < 3) sbh[tid] = *(volatile unsigned*)&g_hflag[tid][0][0];
    if (tid >= 3 && tid < 7) sbx[tid-3] = *(volatile unsigned*)&g_xflag[(tid-3)>>1][(tid-3)&1][0][0];
    if (tid == 7) sg = *(volatile ULL*)&g_gen[0];
    __syncthreads();

    // ================= Phase 0: X1 = seq @ Wih1^T + b =================
    {
        float wx[3], bb[3];
        #pragma unroll
        for (int p = 0; p < 3; p++) {
            int row = cta * 8 + w + p * 896;
            bool v = row < 2048; int R = v ? row : 0;
            wx[p] = v ? Wih1[R * INn + lane] : 0.0f;
            bb[p] = v ? (bih1[R] + bhh1[R]) : 0.0f;
        }
        for (int t0 = 0; t0 < Tn; t0 += 32) {
            __syncthreads();
            {
                const float4 v = *(const float4*)(seq + (size_t)t0 * INn + tid * 4);
                int tl = (tid * 4) >> 5, k = (tid * 4) & 31;
                float* pp = &sseq[tl * 33 + k];
                pp[0] = v.x; pp[1] = v.y; pp[2] = v.z; pp[3] = v.w;
            }
            __syncthreads();
            #pragma unroll
            for (int p = 0; p < 3; p++) {
                int row = cta * 8 + w + p * 896;
                if (row < 2048) {
                    float acc = 0.0f;
                    #pragma unroll
                    for (int k = 0; k < INn; k++)
                        acc = fmaf(__shfl_sync(0xffffffffu, wx[p], k), sseq[lane * 33 + k], acc);
                    g_X[0][(size_t)(t0 + lane) * 2048 + row] = acc + bb[p];
                }
            }
        }
    }
    __syncthreads();

    // ================= role assignment + weight fill =================
    const bool rec = (clu < 3);
    int xi = 0, par = 0, up = 0;
    const float* W; const float* fbi = bih2; const float* fbh = bhh2;
    if (rec) {
        W = (clu == 0) ? Whh1 : (clu == 1) ? Whh2 : Whh3;
    } else {
        int f = clu - 3; xi = f >> 1; par = f & 1; up = xi;
        W = (xi == 0) ? Wih2 : Wih3;
        fbi = (xi == 0) ? bih2 : bih3; fbh = (xi == 0) ? bhh2 : bhh3;
    }

    // 4 rows in regs (64 ULL), 4 rows in smem (128 KB) — R10 proven split
    ULL wreg[64];
    float fb[8];
    #pragma unroll
    for (int i = 0; i < 4; i++) {
        int rl = w * 16 + hf * 8 + i;
        size_t R = (size_t)((rl >> 5) * Hn + crank * 32 + (rl & 31));
        #pragma unroll
        for (int j = 0; j < 16; j++)
            wreg[i * 16 + j] = *(const ULL*)(W + R * Hn + l16 * 32 + j * 2);
    }
    #pragma unroll
    for (int s = 0; s < 4; s++) {
        int rl = w * 16 + hf * 8 + 4 + s;
        size_t R = (size_t)((rl >> 5) * Hn + crank * 32 + (rl & 31));
        #pragma unroll
        for (int j = 0; j < 16; j++)
            wsm[(((w * 4 + s) * 16 + j) << 5) + lane] = *(const ULL*)(W + R * Hn + l16 * 32 + j * 2);
    }
    #pragma unroll
    for (int i = 0; i < 8; i++) {
        int rl = w * 16 + hf * 8 + i;
        int R = (rl >> 5) * Hn + crank * 32 + (rl & 31);
        fb[i] = rec ? 0.0f : (fbi[R] + fbh[R]);
    }

    *(float4*)&hbuf[tid * 4] = make_float4(0.f, 0.f, 0.f, 0.f);
    if (rec && tid == 0) { mbar_init(smem_u32(&mbar[0]), 16); mbar_init(smem_u32(&mbar[1]), 16); }
    __syncthreads();
    if (rec) {
        asm volatile("barrier.cluster.arrive.aligned;" ::: "memory");
        asm volatile("barrier.cluster.wait.aligned;" ::: "memory");
    }

    // one-time global barrier
    if (tid == 0) {
        __threadfence();
        ULL old = atomicAdd(&g_cnt[0], 1ULL);
        if (old == (ULL)(NCTA - 1)) {
            g_cnt[0] = 0ULL; __threadfence(); atomicAdd(&g_gen[0], 1ULL);
        }
        volatile ULL* p = &g_gen[0];
        while (*p < sg + 1) { }
        __threadfence();
    }
    __syncthreads();

    if (rec) {
        // ================= recurrent cluster, layer = clu =================
        const unsigned hb = sbh[clu];
        unsigned* myf = &g_hflag[clu][crank][0];
        float* hout = g_h[clu];
        const float* Xs = g_X[clu];
        const unsigned* xf0 = (clu > 0) ? &g_xflag[clu-1][0][crank][0] : (const unsigned*)0;
        const unsigned* xf1 = (clu > 0) ? &g_xflag[clu-1][1][crank][0] : (const unsigned*)0;
        const unsigned xb0 = (clu > 0) ? sbx[(clu-1)*2+0] : 0u;
        const unsigned xb1 = (clu > 0) ? sbx[(clu-1)*2+1] : 0u;

        const uint32_t mb0 = smem_u32(&mbar[0]);
        // distribute: lane pairs (h_{2p}, h_{2p+1}) p=lane&15 -> swizzled ULL slot p*16+crank
        // lanes 0-15 -> rank w ; lanes 16-31 -> rank w+8
        const uint32_t rdst = mapa_rank(
            smem_u32(&hbull[(unsigned)(l16 * 16 + crank)]),
            (uint32_t)(w + (hf << 3)));
        const uint32_t rbar = mapa_rank(mb0, (uint32_t)(w + (hf << 3)));
        float creg = 0.0f;   // lane u keeps c for unit crank*32+u (replicated per warp)

        // ---- initial X prefetch: slots 0,1 ----
        if (tid >= 224) {
            int idx = tid - 224, gate = idx >> 3, ch = idx & 7;
            #pragma unroll
            for (int s = 0; s < 2; s++) {
                if (clu > 0 && idx == 0) {
                    const unsigned* fp = (s & 1) ? xf1 : xf0;
                    unsigned tgt = ((s & 1) ? xb1 : xb0) + (unsigned)((s >> 1) + 1);
                    while ((int)(ld_acq(fp) - tgt) < 0) { }
                }
                __syncwarp();
                *(float4*)&xring[s * 128 + gate * 32 + ch * 4] =
                    *(const float4*)(Xs + (size_t)s * 2048 + gate * 512 + crank * 32 + ch * 4);
            }
        }
        __syncthreads();

        for (int t = 0; t < Tn; t++) {
            // ---- per-warp wait for h(t-1) ----
            if (t > 0) {
                if (lane == 0) mbar_wait(mb0 + ((t - 1) & 1) * 8, (unsigned)(((t - 1) >> 1) & 1));
                __syncwarp();
            }
            // ---- prefetch X[t+2] into ring (warp 7; safe after wait) ----
            int tp = t + 2;
            if (tid >= 224 && tp < Tn) {
                int idx = tid - 224, gate = idx >> 3, ch = idx & 7;
                if (clu > 0 && idx == 0) {
                    const unsigned* fp = (tp & 1) ? xf1 : xf0;
                    unsigned tgt = ((tp & 1) ? xb1 : xb0) + (unsigned)((tp >> 1) + 1);
                    while ((int)(ld_acq(fp) - tgt) < 0) { }
                }
                __syncwarp();
                *(float4*)&xring[(tp & 3) * 128 + gate * 32 + ch * 4] =
                    *(const float4*)(Xs + (size_t)tp * 2048 + gate * 512 + crank * 32 + ch * 4);
            }

            // ---- GEMV: 8 rows per half-warp ----
            const ULL* hsrc = hbull + ((t + 1) & 1) * 256;
            ULL a0=0,a1=0,a2=0,a3=0,a4=0,a5=0,a6=0,a7=0;
            #pragma unroll
            for (int j = 0; j < 16; j++) {
                ULL hv = hsrc[j * 16 + l16];
                ffma2(a0, wreg[j], hv);       ffma2(a1, wreg[16+j], hv);
                ffma2(a2, wreg[32+j], hv);    ffma2(a3, wreg[48+j], hv);
                ffma2(a4, wsm[(((w*4+0)*16+j)<<5)+lane], hv);
                ffma2(a5, wsm[(((w*4+1)*16+j)<<5)+lane], hv);
                ffma2(a6, wsm[(((w*4+2)*16+j)<<5)+lane], hv);
                ffma2(a7, wsm[(((w*4+3)*16+j)<<5)+lane], hv);
            }
            float r0=f2lo(a0)+f2hi(a0), r1=f2lo(a1)+f2hi(a1), r2=f2lo(a2)+f2hi(a2), r3=f2lo(a3)+f2hi(a3);
            float r4=f2lo(a4)+f2hi(a4), r5=f2lo(a5)+f2hi(a5), r6=f2lo(a6)+f2hi(a6), r7=f2lo(a7)+f2hi(a7);
            RED16(r0) RED16(r1) RED16(r2) RED16(r3) RED16(r4) RED16(r5) RED16(r6) RED16(r7)
            if (l16 == 0) {
                int rb = w * 16 + hf * 8;
                sp[rb]=r0; sp[rb+1]=r1; sp[rb+2]=r2; sp[rb+3]=r3;
                sp[rb+4]=r4; sp[rb+5]=r5; sp[rb+6]=r6; sp[rb+7]=r7;
            }
            __syncthreads();                               // the ONLY block barrier per step

            // ---- redundant epilogue: every warp computes all 32 units ----
            const float* xr = xring + (t & 3) * 128;
            float pi = sp[lane]        + xr[lane];
            float pf = sp[32 + lane]   + xr[32 + lane];
            float pg = sp[64 + lane]   + xr[64 + lane];
            float po = sp[96 + lane]   + xr[96 + lane];
            float iv = fast_sig(pi), fv = fast_sig(pf);
            float gg = fast_tanh(pg), ov = fast_sig(po);
            creg = fmaf(fv, creg, iv * gg);
            float h = ov * fast_tanh(creg);

            // ---- distribute: one st.cluster.u64 per lane ----
            unsigned plo = __shfl_sync(0xffffffffu, __float_as_uint(h), 2 * l16);
            unsigned phi = __shfl_sync(0xffffffffu, __float_as_uint(h), 2 * l16 + 1);
            ULL hv = ((ULL)phi << 32) | plo;
            st_cluster_u64(rdst + (unsigned)(t & 1) * 2048u, hv);
            __syncwarp();
            if (l16 == 0) {
                asm volatile("fence.acq_rel.cluster;" ::: "memory");
                mbar_arrive_cl(rbar + (unsigned)(t & 1) * 8u);
            }

            // ---- g_h write + per-CTA flag (warp 0 only) ----
            if (w == 0) {
                hout[(size_t)t * Hn + crank * 32 + lane] = h;
                __syncwarp();
                if (lane == 0) st_rel(myf, hb + (unsigned)(t + 1));
            }
        }
        asm volatile("barrier.cluster.arrive.aligned;" ::: "memory");
        asm volatile("barrier.cluster.wait.aligned;" ::: "memory");
    } else {
        // ================= feeder: X[xi+1][t] = W . g_h[up][t] + b, parity par =================
        const unsigned ub = sbh[up];
        const unsigned xb = sbx[xi * 2 + par];
        unsigned* myf = &g_xflag[xi][par][crank][0];
        float* Xd = g_X[xi + 1];
        const float* hg = g_h[up];

        for (int t = par; t < Tn; t += 2) {
            if (tid < 16) {
                unsigned tgt = ub + (unsigned)(t + 1);
                const unsigned* fp = &g_hflag[up][tid][0];
                while ((int)(ld_acq(fp) - tgt) < 0) { }
            }
            __syncthreads();
            if (tid < 128) {    // coalesced load, swizzled store
                float4 v = *(const float4*)(hg + (size_t)t * Hn + tid * 4);
                int k0 = 2 * tid, k1 = 2 * tid + 1;
                ULL u0 = ((ULL)__float_as_uint(v.y) << 32) | __float_as_uint(v.x);
                ULL u1 = ((ULL)__float_as_uint(v.w) << 32) | __float_as_uint(v.z);
                hbull[((k0 & 15) << 4) | (k0 >> 4)] = u0;
                hbull[((k1 & 15) << 4) | (k1 >> 4)] = u1;
            }
            __syncthreads();

            const ULL* hsrc = hbull;
            ULL a0=0,a1=0,a2=0,a3=0,a4=0,a5=0,a6=0,a7=0;
            #pragma unroll
            for (int j = 0; j < 16; j++) {
                ULL hv = hsrc[j * 16 + l16];
                ffma2(a0, wreg[j], hv);       ffma2(a1, wreg[16+j], hv);
                ffma2(a2, wreg[32+j], hv);    ffma2(a3, wreg[48+j], hv);
                ffma2(a4, wsm[(((w*4+0)*16+j)<<5)+lane], hv);
                ffma2(a5, wsm[(((w*4+1)*16+j)<<5)+lane], hv);
                ffma2(a6, wsm[(((w*4+2)*16+j)<<5)+lane], hv);
                ffma2(a7, wsm[(((w*4+3)*16+j)<<5)+lane], hv);
            }
            float rr[8];
            rr[0]=f2lo(a0)+f2hi(a0); rr[1]=f2lo(a1)+f2hi(a1); rr[2]=f2lo(a2)+f2hi(a2); rr[3]=f2lo(a3)+f2hi(a3);
            rr[4]=f2lo(a4)+f2hi(a4); rr[5]=f2lo(a5)+f2hi(a5); rr[6]=f2lo(a6)+f2hi(a6); rr[7]=f2lo(a7)+f2hi(a7);
            #pragma unroll
            for (int i = 0; i < 8; i++) { RED16(rr[i]) }
            if (l16 == 0) {
                int rb = w * 16 + hf * 8;
                #pragma unroll
                for (int i = 0; i < 8; i++) {
                    int rl = rb + i;
                    Xd[(size_t)t * 2048 + (rl >> 5) * 512 + crank * 32 + (rl & 31)] = rr[i] + fb[i];
                }
            }
            __syncthreads();
            if (tid == 0) st_rel(myf, xb + (unsigned)((t >> 1) + 1));
        }
    }

    // ================= final projection (all CTAs) =================
    if (tid < 16) {
        unsigned tgt = sbh[2] + (unsigned)Tn;
        const unsigned* fp = &g_hflag[2][tid][0];
        while ((int)(ld_acq(fp) - tgt) < 0) { }
    }
    __syncthreads();

    ULL wo[32];
    float bo4[4];
    #pragma unroll
    for (int oi = 0; oi < 4; oi++) {
        int o = w * 4 + oi;
        #pragma unroll
        for (int j = 0; j < 8; j++)
            wo[oi * 8 + j] = *(const ULL*)(Wout + (size_t)o * Hn + j * 64 + lane * 2);
        bo4[oi] = bout[o];
    }
    const float* h3 = g_h[2];
    for (int t = cta; t < Tn; t += NCTA) {
        __syncthreads();
        if (tid < 128)
            *(float4*)&hbuf[tid * 4] = *(const float4*)(h3 + (size_t)t * Hn + tid * 4);
        __syncthreads();
        const ULL* hh = (const ULL*)hbuf;
        #pragma unroll
        for (int oi = 0; oi < 4; oi++) {
            ULL acc = 0;
            #pragma unroll
            for (int j = 0; j < 8; j++) ffma2(acc, wo[oi * 8 + j], hh[j * 32 + lane]);
            float r = f2lo(acc) + f2hi(acc);
            RED32(r)
            if (lane == 0) out[(size_t)t * OUTn + w * 4 + oi] = r + bo4[oi];
        }
    }
}

extern "C" void kernel_launch(void* const* d_in, const int* in_sizes, int n_in,
                              void* d_out, int out_size) {
    const float* seq  = (const float*)d_in[0];
    const float* Wih1 = (const float*)d_in[1];
    const float* Whh1 = (const float*)d_in[2];
    const float* bih1 = (const float*)d_in[3];
    const float* bhh1 = (const float*)d_in[4];
    const float* Wih2 = (const float*)d_in[5];
    const float* Whh2 = (const float*)d_in[6];
    const float* bih2 = (const float*)d_in[7];
    const float* bhh2 = (const float*)d_in[8];
    const float* Wih3 = (const float*)d_in[9];
    const float* Whh3 = (const float*)d_in[10];
    const float* bih3 = (const float*)d_in[11];
    const float* bhh3 = (const float*)d_in[12];
    const float* Wout = (const float*)d_in[13];
    const float* bout = (const float*)d_in[14];
    float* out = (float*)d_out;

    cudaFuncSetAttribute(lstm_pipe2_kernel, cudaFuncAttributeMaxDynamicSharedMemorySize, SMEM_SZ);
    cudaFuncSetAttribute(lstm_pipe2_kernel, cudaFuncAttributeNonPortableClusterSizeAllowed, 1);

    cudaLaunchConfig_t cfg = {};
    cfg.gridDim = {NCTA, 1, 1};
    cfg.blockDim = {TPB, 1, 1};
    cfg.dynamicSmemBytes = SMEM_SZ;
    cudaLaunchAttribute at[1];
    at[0].id = cudaLaunchAttributeClusterDimension;
    at[0].val.clusterDim = {CLC, 1, 1};
    cfg.attrs = at;
    cfg.numAttrs = 1;

    cudaLaunchKernelEx(&cfg, lstm_pipe2_kernel, seq,
        Wih1, Whh1, bih1, bhh1,
        Wih2, Whh2, bih2, bhh2,
        Wih3, Whh3, bih3, bhh3,
        Wout, bout, out);
}